// round 15
// baseline (speedup 1.0000x reference)
#include <cuda_runtime.h>
#include <cuda_bf16.h>
#include <cstddef>

// ---------------------------------------------------------------------------
// Swin shifted-window attention, fp32, f32x2-packed FFMA throughout.
//   B=32, H=W=56, HIDDEN=96, HEADS=3, HD=32, WS=7, DISP=3
//   nw_h=nw_w=8, nw=64, tokens/window=49
// ---------------------------------------------------------------------------

typedef unsigned long long ull;

__device__ __forceinline__ void ffma2(ull& d, ull a, ull b) {
    // d.lo += a.lo*b.lo ; d.hi += a.hi*b.hi   (packed fp32x2 FMA, sm_100+)
    asm("fma.rn.f32x2 %0, %1, %2, %0;" : "+l"(d) : "l"(a), "l"(b));
}
__device__ __forceinline__ ull pack2(float lo, float hi) {
    ull r; asm("mov.b64 %0, {%1, %2};" : "=l"(r) : "f"(lo), "f"(hi)); return r;
}
__device__ __forceinline__ float2 unpack2(ull p) {
    float2 r; asm("mov.b64 {%0, %1}, %2;" : "=f"(r.x), "=f"(r.y) : "l"(p)); return r;
}
__device__ __forceinline__ float sum2(ull p) {
    float2 r = unpack2(p); return r.x + r.y;
}

// Scratch (allocation-free rule: __device__ globals).
// Layout of q/k/v: [b][head][win][tok 0..48][d 0..31]
#define NTOK (32 * 56 * 56)                 // 100352
__device__ float g_q[NTOK * 96];            // 38.5 MB each
__device__ float g_k[NTOK * 96];
__device__ float g_v[NTOK * 96];
__device__ float g_att[NTOK * 96];          // attention output in [B,H,W,96] (shifted coords)

// ---------------------------------------------------------------------------
// Kernel 1: cyclic shift + QKV GEMM + window rearrange.
// One block per (b, window). 288 threads: thread n owns output column n of
// the [49 x 288] tile. Rows processed in two passes of 25 to bound registers.
// ---------------------------------------------------------------------------
__global__ __launch_bounds__(288, 2) void k_qkv(const float* __restrict__ x,
                                                const float* __restrict__ wq,
                                                const float* __restrict__ bq) {
    const int b   = blockIdx.x >> 6;
    const int win = blockIdx.x & 63;
    const int wh  = win >> 3, ww = win & 7;

    __shared__ __align__(16) float xs[50 * 96];   // 49 valid rows + 1 pad row

    const int tid = threadIdx.x;

    // Load shifted window rows (each row = 96 contiguous floats of x).
    for (int idx = tid; idx < 49 * 24; idx += 288) {
        const int i  = idx / 24;
        const int q4 = idx - i * 24;
        const int sh = (wh * 7 + i / 7 + 3) % 56;
        const int sw = (ww * 7 + i % 7 + 3) % 56;
        reinterpret_cast<float4*>(xs)[idx] =
            reinterpret_cast<const float4*>(x + ((size_t)((b * 56 + sh) * 56 + sw)) * 96)[q4];
    }
    __syncthreads();

    const int n    = tid;                  // 0..287
    const float bn = bq[n];
    const int part = n / 96;               // 0=q,1=k,2=v
    const int c    = n - part * 96;        // channel within q/k/v
    float* buf  = (part == 0) ? g_q : (part == 1) ? g_k : g_v;
    float* base = buf + ((size_t)(((b * 3 + (c >> 5)) * 64 + win)) * 49) * 32 + (c & 31);

    #pragma unroll 1
    for (int pass = 0; pass < 2; ++pass) {
        const float* xrow = xs + pass * 25 * 96;
        ull acc[25];
        #pragma unroll
        for (int ii = 0; ii < 25; ++ii) acc[ii] = 0ull;

        #pragma unroll 1
        for (int k = 0; k < 96; k += 4) {
            const float* wp = wq + (size_t)k * 288 + n;   // coalesced across threads
            const ull w01 = pack2(wp[0],   wp[288]);
            const ull w23 = pack2(wp[576], wp[864]);
            #pragma unroll
            for (int ii = 0; ii < 25; ++ii) {
                const ulonglong2 xv = *reinterpret_cast<const ulonglong2*>(xrow + ii * 96 + k);
                ffma2(acc[ii], xv.x, w01);
                ffma2(acc[ii], xv.y, w23);
            }
        }
        #pragma unroll
        for (int ii = 0; ii < 25; ++ii) {
            const int i = pass * 25 + ii;
            if (i < 49) base[i * 32] = sum2(acc[ii]) + bn;
        }
    }
}

// ---------------------------------------------------------------------------
// Kernel 2: per-(b, win, head) attention. 64 threads, thread i<49 owns query
// row i. Scores + relative-position bias + shifted-window mask + softmax in
// registers; PV with packed FFMA2. Writes spatial [B,H,W,96] layout directly.
// ---------------------------------------------------------------------------
__global__ __launch_bounds__(64) void k_attn(const float* __restrict__ pos) {
    const int win  = blockIdx.x;   // 0..63
    const int head = blockIdx.y;   // 0..2
    const int b    = blockIdx.z;   // 0..31

    __shared__ __align__(16) float ks[49 * 32];
    __shared__ __align__(16) float vs[49 * 32];
    __shared__ float ps[169];

    const int tid = threadIdx.x;
    const size_t off = (size_t)(((b * 3 + head) * 64 + win)) * 49 * 32;

    {
        const float4* kb = reinterpret_cast<const float4*>(g_k + off);
        const float4* vb = reinterpret_cast<const float4*>(g_v + off);
        for (int idx = tid; idx < 49 * 8; idx += 64) {
            reinterpret_cast<float4*>(ks)[idx] = kb[idx];
            reinterpret_cast<float4*>(vs)[idx] = vb[idx];
        }
        for (int idx = tid; idx < 169; idx += 64) ps[idx] = pos[idx];
    }
    __syncthreads();

    if (tid >= 49) return;

    const int iy = tid / 7, ix = tid - iy * 7;
    const int pbase = 84 - iy * 13 - ix;          // (6-iy)*13 + (6-ix)

    // q row -> registers (contiguous 128B per thread; warp covers adjacent rows)
    ull q2[16];
    {
        const ulonglong2* qp = reinterpret_cast<const ulonglong2*>(g_q + off + (size_t)tid * 32);
        #pragma unroll
        for (int d4 = 0; d4 < 8; ++d4) {
            const ulonglong2 t = qp[d4];
            q2[2 * d4]     = t.x;
            q2[2 * d4 + 1] = t.y;
        }
    }

    const float scale = 0.10206207261596575f;     // 96^-0.5 (HIDDEN**-0.5)
    const bool  mw    = (win >= 56);              // bottom row of windows gets ul_mask
    const bool  ihigh = (tid >= 28);

    float s[49];
    #pragma unroll
    for (int jy = 0; jy < 7; ++jy) {
        #pragma unroll
        for (int jx = 0; jx < 7; ++jx) {
            const int j = jy * 7 + jx;
            ull acc = 0ull;
            const ulonglong2* kr = reinterpret_cast<const ulonglong2*>(ks + j * 32);
            #pragma unroll
            for (int d4 = 0; d4 < 8; ++d4) {
                const ulonglong2 kv = kr[d4];   // broadcast across threads
                ffma2(acc, q2[2 * d4],     kv.x);
                ffma2(acc, q2[2 * d4 + 1], kv.y);
            }
            float val = sum2(acc) * scale + ps[jy * 13 + jx + pbase];
            if (mw && (ihigh != (j >= 28))) val = -1e30f;
            s[j] = val;
        }
    }

    // softmax over j (row owned by this thread)
    float m = s[0];
    #pragma unroll
    for (int j = 1; j < 49; ++j) m = fmaxf(m, s[j]);
    float sum = 0.f;
    #pragma unroll
    for (int j = 0; j < 49; ++j) { s[j] = __expf(s[j] - m); sum += s[j]; }
    const float inv = __fdividef(1.f, sum);

    // out = P @ V
    ull o2[16];
    #pragma unroll
    for (int d = 0; d < 16; ++d) o2[d] = 0ull;
    #pragma unroll
    for (int j = 0; j < 49; ++j) {
        const float p = s[j] * inv;
        const ull p2 = pack2(p, p);
        const ulonglong2* vr = reinterpret_cast<const ulonglong2*>(vs + j * 32);
        #pragma unroll
        for (int d4 = 0; d4 < 8; ++d4) {
            const ulonglong2 vv = vr[d4];
            ffma2(o2[2 * d4],     p2, vv.x);
            ffma2(o2[2 * d4 + 1], p2, vv.y);
        }
    }

    // un-window: write to spatial [B,H,W,96] (still in shifted coordinates)
    const int h = (win >> 3) * 7 + iy;
    const int w = (win & 7) * 7 + ix;
    float* dst = g_att + ((size_t)((b * 56 + h) * 56 + w)) * 96 + head * 32;
    #pragma unroll
    for (int d4 = 0; d4 < 8; ++d4) {
        const float2 a = unpack2(o2[2 * d4]);
        const float2 c = unpack2(o2[2 * d4 + 1]);
        reinterpret_cast<float4*>(dst)[d4] = make_float4(a.x, a.y, c.x, c.y);
    }
}

// ---------------------------------------------------------------------------
// Kernel 3: output projection [.,96]x[96,96] + bias, inverse roll fused into
// the store index. 32 rows per block, 96 threads (thread n = output column).
// ---------------------------------------------------------------------------
__global__ __launch_bounds__(96) void k_out(const float* __restrict__ wo,
                                            const float* __restrict__ bo,
                                            float* __restrict__ out) {
    const int r0  = blockIdx.x * 32;
    const int tid = threadIdx.x;

    __shared__ __align__(16) float xs[32 * 96];
    {
        const float4* src = reinterpret_cast<const float4*>(g_att + (size_t)r0 * 96);
        for (int idx = tid; idx < 32 * 24; idx += 96)
            reinterpret_cast<float4*>(xs)[idx] = src[idx];
    }
    __syncthreads();

    const int n    = tid;
    const float bn = bo[n];
    ull acc[32];
    #pragma unroll
    for (int ii = 0; ii < 32; ++ii) acc[ii] = 0ull;

    #pragma unroll 1
    for (int k = 0; k < 96; k += 4) {
        const float* wp = wo + (size_t)k * 96 + n;
        const ull w01 = pack2(wp[0],   wp[96]);
        const ull w23 = pack2(wp[192], wp[288]);
        #pragma unroll
        for (int ii = 0; ii < 32; ++ii) {
            const ulonglong2 xv = *reinterpret_cast<const ulonglong2*>(xs + ii * 96 + k);
            ffma2(acc[ii], xv.x, w01);
            ffma2(acc[ii], xv.y, w23);
        }
    }

    #pragma unroll
    for (int ii = 0; ii < 32; ++ii) {
        const int r   = r0 + ii;
        const int bb  = r / 3136;
        const int rem = r - bb * 3136;
        const int h   = rem / 56;
        const int w   = rem - h * 56;
        // final = roll(y, (+3,+3)): out[(h+3)%56][(w+3)%56] = y[h][w]
        out[((size_t)((bb * 56 + (h + 3) % 56) * 56 + (w + 3) % 56)) * 96 + n]
            = sum2(acc[ii]) + bn;
    }
}

// ---------------------------------------------------------------------------
extern "C" void kernel_launch(void* const* d_in, const int* in_sizes, int n_in,
                              void* d_out, int out_size) {
    // Map inputs by element count (all counts are distinct):
    //   x=9633792, w_qkv=27648, b_qkv=288, pos=169, w_out=9216, b_out=96
    const float *x = nullptr, *wq = nullptr, *bq = nullptr,
                *pos = nullptr, *wo = nullptr, *bo = nullptr;
    for (int i = 0; i < n_in; ++i) {
        switch (in_sizes[i]) {
            case 9633792: x   = (const float*)d_in[i]; break;
            case 27648:   wq  = (const float*)d_in[i]; break;
            case 288:     bq  = (const float*)d_in[i]; break;
            case 169:     pos = (const float*)d_in[i]; break;
            case 9216:    wo  = (const float*)d_in[i]; break;
            case 96:      bo  = (const float*)d_in[i]; break;
            default: break;
        }
    }
    float* out = (float*)d_out;

    k_qkv <<<2048, 288>>>(x, wq, bq);
    k_attn<<<dim3(64, 3, 32), 64>>>(pos);
    k_out <<<3136, 96>>>(wo, bo, out);
}

// round 16
// speedup vs baseline: 1.0024x; 1.0024x over previous
#include <cuda_runtime.h>
#include <cuda_bf16.h>
#include <cstddef>

// ---------------------------------------------------------------------------
// Swin shifted-window attention, fp32, f32x2-packed FFMA throughout.
//   B=32, H=W=56, HIDDEN=96, HEADS=3, HD=32, WS=7, DISP=3
//   nw_h=nw_w=8, nw=64, tokens/window=49
// ---------------------------------------------------------------------------

typedef unsigned long long ull;

__device__ __forceinline__ void ffma2(ull& d, ull a, ull b) {
    // d.lo += a.lo*b.lo ; d.hi += a.hi*b.hi   (packed fp32x2 FMA, sm_100+)
    asm("fma.rn.f32x2 %0, %1, %2, %0;" : "+l"(d) : "l"(a), "l"(b));
}
__device__ __forceinline__ ull pack2(float lo, float hi) {
    ull r; asm("mov.b64 %0, {%1, %2};" : "=l"(r) : "f"(lo), "f"(hi)); return r;
}
__device__ __forceinline__ float2 unpack2(ull p) {
    float2 r; asm("mov.b64 {%0, %1}, %2;" : "=f"(r.x), "=f"(r.y) : "l"(p)); return r;
}
__device__ __forceinline__ float sum2(ull p) {
    float2 r = unpack2(p); return r.x + r.y;
}

// Scratch (allocation-free rule: __device__ globals).
// Layout of q/k/v: [b][head][win][tok 0..48][d 0..31]
#define NTOK (32 * 56 * 56)                 // 100352
__device__ float g_q[NTOK * 96];            // 38.5 MB each
__device__ float g_k[NTOK * 96];
__device__ float g_v[NTOK * 96];
__device__ float g_att[NTOK * 96];          // attention output in [B,H,W,96] (shifted coords)

// ---------------------------------------------------------------------------
// Kernel 1: cyclic shift + QKV GEMM + window rearrange.
// One block per (b, window). 288 threads: thread n owns output column n of
// the [49 x 288] tile. Rows processed in two passes of 25 to bound registers.
// ---------------------------------------------------------------------------
__global__ __launch_bounds__(288, 2) void k_qkv(const float* __restrict__ x,
                                                const float* __restrict__ wq,
                                                const float* __restrict__ bq) {
    const int b   = blockIdx.x >> 6;
    const int win = blockIdx.x & 63;
    const int wh  = win >> 3, ww = win & 7;

    __shared__ __align__(16) float xs[50 * 96];   // 49 valid rows + 1 pad row

    const int tid = threadIdx.x;

    // Load shifted window rows (each row = 96 contiguous floats of x).
    for (int idx = tid; idx < 49 * 24; idx += 288) {
        const int i  = idx / 24;
        const int q4 = idx - i * 24;
        const int sh = (wh * 7 + i / 7 + 3) % 56;
        const int sw = (ww * 7 + i % 7 + 3) % 56;
        reinterpret_cast<float4*>(xs)[idx] =
            reinterpret_cast<const float4*>(x + ((size_t)((b * 56 + sh) * 56 + sw)) * 96)[q4];
    }
    __syncthreads();

    const int n    = tid;                  // 0..287
    const float bn = bq[n];
    const int part = n / 96;               // 0=q,1=k,2=v
    const int c    = n - part * 96;        // channel within q/k/v
    float* buf  = (part == 0) ? g_q : (part == 1) ? g_k : g_v;
    float* base = buf + ((size_t)(((b * 3 + (c >> 5)) * 64 + win)) * 49) * 32 + (c & 31);

    #pragma unroll 1
    for (int pass = 0; pass < 2; ++pass) {
        const float* xrow = xs + pass * 25 * 96;
        ull acc[25];
        #pragma unroll
        for (int ii = 0; ii < 25; ++ii) acc[ii] = 0ull;

        #pragma unroll 1
        for (int k = 0; k < 96; k += 4) {
            const float* wp = wq + (size_t)k * 288 + n;   // coalesced across threads
            const ull w01 = pack2(wp[0],   wp[288]);
            const ull w23 = pack2(wp[576], wp[864]);
            #pragma unroll
            for (int ii = 0; ii < 25; ++ii) {
                const ulonglong2 xv = *reinterpret_cast<const ulonglong2*>(xrow + ii * 96 + k);
                ffma2(acc[ii], xv.x, w01);
                ffma2(acc[ii], xv.y, w23);
            }
        }
        #pragma unroll
        for (int ii = 0; ii < 25; ++ii) {
            const int i = pass * 25 + ii;
            if (i < 49) base[i * 32] = sum2(acc[ii]) + bn;
        }
    }
}

// ---------------------------------------------------------------------------
// Kernel 2: per-(b, win, head) attention. 64 threads, thread i<49 owns query
// row i. Scores + relative-position bias + shifted-window mask + softmax in
// registers; PV with packed FFMA2. Writes spatial [B,H,W,96] layout directly.
// ---------------------------------------------------------------------------
__global__ __launch_bounds__(64) void k_attn(const float* __restrict__ pos) {
    const int win  = blockIdx.x;   // 0..63
    const int head = blockIdx.y;   // 0..2
    const int b    = blockIdx.z;   // 0..31

    __shared__ __align__(16) float ks[49 * 32];
    __shared__ __align__(16) float vs[49 * 32];
    __shared__ float ps[169];

    const int tid = threadIdx.x;
    const size_t off = (size_t)(((b * 3 + head) * 64 + win)) * 49 * 32;

    {
        const float4* kb = reinterpret_cast<const float4*>(g_k + off);
        const float4* vb = reinterpret_cast<const float4*>(g_v + off);
        for (int idx = tid; idx < 49 * 8; idx += 64) {
            reinterpret_cast<float4*>(ks)[idx] = kb[idx];
            reinterpret_cast<float4*>(vs)[idx] = vb[idx];
        }
        for (int idx = tid; idx < 169; idx += 64) ps[idx] = pos[idx];
    }
    __syncthreads();

    if (tid >= 49) return;

    const int iy = tid / 7, ix = tid - iy * 7;
    const int pbase = 84 - iy * 13 - ix;          // (6-iy)*13 + (6-ix)

    // q row -> registers (contiguous 128B per thread; warp covers adjacent rows)
    ull q2[16];
    {
        const ulonglong2* qp = reinterpret_cast<const ulonglong2*>(g_q + off + (size_t)tid * 32);
        #pragma unroll
        for (int d4 = 0; d4 < 8; ++d4) {
            const ulonglong2 t = qp[d4];
            q2[2 * d4]     = t.x;
            q2[2 * d4 + 1] = t.y;
        }
    }

    const float scale = 0.10206207261596575f;     // 96^-0.5 (HIDDEN**-0.5)
    const bool  mw    = (win >= 56);              // bottom row of windows gets ul_mask
    const bool  ihigh = (tid >= 28);

    float s[49];
    #pragma unroll
    for (int jy = 0; jy < 7; ++jy) {
        #pragma unroll
        for (int jx = 0; jx < 7; ++jx) {
            const int j = jy * 7 + jx;
            ull acc = 0ull;
            const ulonglong2* kr = reinterpret_cast<const ulonglong2*>(ks + j * 32);
            #pragma unroll
            for (int d4 = 0; d4 < 8; ++d4) {
                const ulonglong2 kv = kr[d4];   // broadcast across threads
                ffma2(acc, q2[2 * d4],     kv.x);
                ffma2(acc, q2[2 * d4 + 1], kv.y);
            }
            float val = sum2(acc) * scale + ps[jy * 13 + jx + pbase];
            if (mw && (ihigh != (j >= 28))) val = -1e30f;
            s[j] = val;
        }
    }

    // softmax over j (row owned by this thread)
    float m = s[0];
    #pragma unroll
    for (int j = 1; j < 49; ++j) m = fmaxf(m, s[j]);
    float sum = 0.f;
    #pragma unroll
    for (int j = 0; j < 49; ++j) { s[j] = __expf(s[j] - m); sum += s[j]; }
    const float inv = __fdividef(1.f, sum);

    // out = P @ V
    ull o2[16];
    #pragma unroll
    for (int d = 0; d < 16; ++d) o2[d] = 0ull;
    #pragma unroll
    for (int j = 0; j < 49; ++j) {
        const float p = s[j] * inv;
        const ull p2 = pack2(p, p);
        const ulonglong2* vr = reinterpret_cast<const ulonglong2*>(vs + j * 32);
        #pragma unroll
        for (int d4 = 0; d4 < 8; ++d4) {
            const ulonglong2 vv = vr[d4];
            ffma2(o2[2 * d4],     p2, vv.x);
            ffma2(o2[2 * d4 + 1], p2, vv.y);
        }
    }

    // un-window: write to spatial [B,H,W,96] (still in shifted coordinates)
    const int h = (win >> 3) * 7 + iy;
    const int w = (win & 7) * 7 + ix;
    float* dst = g_att + ((size_t)((b * 56 + h) * 56 + w)) * 96 + head * 32;
    #pragma unroll
    for (int d4 = 0; d4 < 8; ++d4) {
        const float2 a = unpack2(o2[2 * d4]);
        const float2 c = unpack2(o2[2 * d4 + 1]);
        reinterpret_cast<float4*>(dst)[d4] = make_float4(a.x, a.y, c.x, c.y);
    }
}

// ---------------------------------------------------------------------------
// Kernel 3: output projection [.,96]x[96,96] + bias, inverse roll fused into
// the store index. 32 rows per block, 96 threads (thread n = output column).
// ---------------------------------------------------------------------------
__global__ __launch_bounds__(96) void k_out(const float* __restrict__ wo,
                                            const float* __restrict__ bo,
                                            float* __restrict__ out) {
    const int r0  = blockIdx.x * 32;
    const int tid = threadIdx.x;

    __shared__ __align__(16) float xs[32 * 96];
    {
        const float4* src = reinterpret_cast<const float4*>(g_att + (size_t)r0 * 96);
        for (int idx = tid; idx < 32 * 24; idx += 96)
            reinterpret_cast<float4*>(xs)[idx] = src[idx];
    }
    __syncthreads();

    const int n    = tid;
    const float bn = bo[n];
    ull acc[32];
    #pragma unroll
    for (int ii = 0; ii < 32; ++ii) acc[ii] = 0ull;

    #pragma unroll 1
    for (int k = 0; k < 96; k += 4) {
        const float* wp = wo + (size_t)k * 96 + n;
        const ull w01 = pack2(wp[0],   wp[96]);
        const ull w23 = pack2(wp[192], wp[288]);
        #pragma unroll
        for (int ii = 0; ii < 32; ++ii) {
            const ulonglong2 xv = *reinterpret_cast<const ulonglong2*>(xs + ii * 96 + k);
            ffma2(acc[ii], xv.x, w01);
            ffma2(acc[ii], xv.y, w23);
        }
    }

    #pragma unroll
    for (int ii = 0; ii < 32; ++ii) {
        const int r   = r0 + ii;
        const int bb  = r / 3136;
        const int rem = r - bb * 3136;
        const int h   = rem / 56;
        const int w   = rem - h * 56;
        // final = roll(y, (+3,+3)): out[(h+3)%56][(w+3)%56] = y[h][w]
        out[((size_t)((bb * 56 + (h + 3) % 56) * 56 + (w + 3) % 56)) * 96 + n]
            = sum2(acc[ii]) + bn;
    }
}

// ---------------------------------------------------------------------------
extern "C" void kernel_launch(void* const* d_in, const int* in_sizes, int n_in,
                              void* d_out, int out_size) {
    // Map inputs by element count (all counts are distinct):
    //   x=9633792, w_qkv=27648, b_qkv=288, pos=169, w_out=9216, b_out=96
    const float *x = nullptr, *wq = nullptr, *bq = nullptr,
                *pos = nullptr, *wo = nullptr, *bo = nullptr;
    for (int i = 0; i < n_in; ++i) {
        switch (in_sizes[i]) {
            case 9633792: x   = (const float*)d_in[i]; break;
            case 27648:   wq  = (const float*)d_in[i]; break;
            case 288:     bq  = (const float*)d_in[i]; break;
            case 169:     pos = (const float*)d_in[i]; break;
            case 9216:    wo  = (const float*)d_in[i]; break;
            case 96:      bo  = (const float*)d_in[i]; break;
            default: break;
        }
    }
    float* out = (float*)d_out;

    k_qkv <<<2048, 288>>>(x, wq, bq);
    k_attn<<<dim3(64, 3, 32), 64>>>(pos);
    k_out <<<3136, 96>>>(wo, bo, out);
}